// round 15
// baseline (speedup 1.0000x reference)
#include <cuda_runtime.h>
#include <cuda_bf16.h>
#include <math.h>

#define BATCH 64
#define SEQ   196
#define DIMC  768
#define HEADS 12
#define HD    64
#define QKV3  2304           // 3*DIMC
#define BN    (BATCH*SEQ)    // 12544
#define SCALE 0.125f         // HD^-0.5
#define NBLK  (BATCH*HEADS*2)  // 1536 (b,h,q-half)

// ---------------- scratch (no allocation allowed; __device__ globals) -------
__device__ float g_qkv[(size_t)BATCH * SEQ * QKV3];          // [BN, 2304]
__device__ float g_ao[(size_t)BATCH * SEQ * DIMC];           // [BN, 768]

// ---------------- tf32 helpers ----------------------------------------------
__device__ __forceinline__ unsigned f2tf32(float x) {
    unsigned u;
    asm volatile("cvt.rna.tf32.f32 %0, %1;" : "=r"(u) : "f"(x));
    return u;
}

__device__ __forceinline__ void mma_tf32(float (&d)[4], const unsigned (&a)[4],
                                         const unsigned (&b)[2]) {
    asm volatile(
        "mma.sync.aligned.m16n8k8.row.col.f32.tf32.tf32.f32 "
        "{%0,%1,%2,%3}, {%4,%5,%6,%7}, {%8,%9}, {%0,%1,%2,%3};\n"
        : "+f"(d[0]), "+f"(d[1]), "+f"(d[2]), "+f"(d[3])
        : "r"(a[0]), "r"(a[1]), "r"(a[2]), "r"(a[3]), "r"(b[0]), "r"(b[1]));
}

// ---------------- TF32 GEMM: 128x128 tile, 128 threads, warp tile 64x64 -----
// 4 warps (2M x 2N). Frag crossbar traffic per tile: 64KB (vs 96KB with the
// 32x64 warp tile) + 32KB STS -> 25% fewer crossbar bytes per flop.
#define TBM 128
#define TBN 128
#define TBK 32
#define AS_STRIDE 36    // %32==4 -> A frag banks (4r+tq) all distinct
#define BS_STRIDE 136   // %32==8 -> B frag banks (8tq+r) all distinct

__global__ __launch_bounds__(128, 2)
void gemm_tf32_kernel(const float* __restrict__ A, const float* __restrict__ B,
                      const float* __restrict__ bias, float* __restrict__ C,
                      int M, int N, int K, int useBias)
{
    __shared__ unsigned As[TBM * AS_STRIDE];   // [m][k]
    __shared__ unsigned Bs[TBK * BS_STRIDE];   // [k][n]

    const int tid  = threadIdx.x;
    const int lane = tid & 31;
    const int warp = tid >> 5;            // 0..3
    const int r    = lane >> 2;
    const int tq   = lane & 3;
    const int warpM = (warp & 1) * 64;    // 2 warps in M
    const int warpN = (warp >> 1) * 64;   // 2 warps in N

    const int n0 = blockIdx.x * TBN;
    const int m0 = blockIdx.y * TBM;

    float acc[4][8][4];
#pragma unroll
    for (int i = 0; i < 4; i++)
#pragma unroll
        for (int j = 0; j < 8; j++)
#pragma unroll
            for (int t = 0; t < 4; t++) acc[i][j][t] = 0.f;

    for (int k0 = 0; k0 < K; k0 += TBK) {
        // ---- load A tile: 128 rows x 32 k = 1024 float4 (8 per thread)
#pragma unroll
        for (int i = 0; i < 8; i++) {
            int f   = tid + i * 128;
            int row = f >> 3;                 // 0..127
            int kk  = (f & 7) * 4;            // 0..28
            float4 v = *(const float4*)(A + (size_t)(m0 + row) * K + k0 + kk);
            uint4 o;
            o.x = f2tf32(v.x); o.y = f2tf32(v.y);
            o.z = f2tf32(v.z); o.w = f2tf32(v.w);
            *(uint4*)&As[row * AS_STRIDE + kk] = o;
        }
        // ---- load B tile: 32 k x 128 n = 1024 float4 (8 per thread)
#pragma unroll
        for (int i = 0; i < 8; i++) {
            int f   = tid + i * 128;
            int kk  = f >> 5;                 // 0..31
            int nn  = (f & 31) * 4;           // 0..124
            float4 v = *(const float4*)(B + (size_t)(k0 + kk) * N + n0 + nn);
            uint4 o;
            o.x = f2tf32(v.x); o.y = f2tf32(v.y);
            o.z = f2tf32(v.z); o.w = f2tf32(v.w);
            *(uint4*)&Bs[kk * BS_STRIDE + nn] = o;
        }
        __syncthreads();

        // ---- compute: 4 k-steps of 8; B frags loaded once per ks,
        //      A frags per (ks, mt)
#pragma unroll
        for (int ks = 0; ks < 4; ks++) {
            int kb = ks * 8;
            unsigned bfrag[8][2];
#pragma unroll
            for (int nt = 0; nt < 8; nt++) {
                int cb = warpN + nt * 8;
                bfrag[nt][0] = Bs[(kb + tq)     * BS_STRIDE + cb + r];
                bfrag[nt][1] = Bs[(kb + tq + 4) * BS_STRIDE + cb + r];
            }
#pragma unroll
            for (int mt = 0; mt < 4; mt++) {
                int rb = warpM + mt * 16;
                unsigned af[4];
                af[0] = As[(rb + r)     * AS_STRIDE + kb + tq];
                af[1] = As[(rb + r + 8) * AS_STRIDE + kb + tq];
                af[2] = As[(rb + r)     * AS_STRIDE + kb + tq + 4];
                af[3] = As[(rb + r + 8) * AS_STRIDE + kb + tq + 4];
#pragma unroll
                for (int nt = 0; nt < 8; nt++)
                    mma_tf32(acc[mt][nt], af, bfrag[nt]);
            }
        }
        __syncthreads();
    }

    // ---- epilogue: c0/c1 at (r, 2tq), c2/c3 at (r+8, 2tq)
#pragma unroll
    for (int mt = 0; mt < 4; mt++) {
#pragma unroll
        for (int nt = 0; nt < 8; nt++) {
            int row = m0 + warpM + mt * 16 + r;
            int col = n0 + warpN + nt * 8 + 2 * tq;
            float2 lo = make_float2(acc[mt][nt][0], acc[mt][nt][1]);
            float2 hi = make_float2(acc[mt][nt][2], acc[mt][nt][3]);
            if (useBias) {
                float2 bv = *(const float2*)(bias + col);
                lo.x += bv.x; lo.y += bv.y;
                hi.x += bv.x; hi.y += bv.y;
            }
            *(float2*)(C + (size_t)row * N + col)       = lo;
            *(float2*)(C + (size_t)(row + 8) * N + col) = hi;
        }
    }
}

// ---------------- fused attention: scores + reg softmax + bias + AV ---------
// (R14 kernel, unchanged — verified bit-identical numerics)
#define FA_KV_OFF 7616                            // words (112*68)
#define FA_SMEM_WORDS (FA_KV_OFF + 208 * 72)      // 22592
#define FA_SMEM_BYTES (FA_SMEM_WORDS * 4)         // 90368

__global__ __launch_bounds__(224, 2)
void attn_fused_kernel(const float* __restrict__ qkv,
                       const float* __restrict__ sa,
                       float* __restrict__ ao)
{
    extern __shared__ unsigned smu[];
    unsigned* Qs = smu;                 // [112][68], SCALE pre-folded
    unsigned* Ks = smu + FA_KV_OFF;     // [208][68] (scores phase)
    unsigned* Vs = smu + FA_KV_OFF;     // [208][72] tf32 (AV phase)

    const int bid = blockIdx.x;
    const int bh = bid >> 1, qb = bid & 1;
    const int b = bh / HEADS, h = bh % HEADS;
    const int q0 = qb * 98;

    const float* Qg = qkv + (size_t)b * SEQ * QKV3 + h * HD;
    const float* Kg = Qg + DIMC;
    const float* Vg = Qg + 2 * DIMC;

    const int tid  = threadIdx.x;
    const int lane = tid & 31;
    const int warp = tid >> 5;
    const int r    = lane >> 2;
    const int tq   = lane & 3;

    // ---- load Q (tf32, pre-scaled), rows >= 98 zeroed
    for (int i = tid; i < 112 * 16; i += 224) {
        int row = i >> 4, c4 = (i & 15) * 4;
        float4 v = make_float4(0.f, 0.f, 0.f, 0.f);
        if (row < 98) v = *(const float4*)(Qg + (size_t)(q0 + row) * QKV3 + c4);
        uint4 o;
        o.x = f2tf32(v.x * SCALE); o.y = f2tf32(v.y * SCALE);
        o.z = f2tf32(v.z * SCALE); o.w = f2tf32(v.w * SCALE);
        *(uint4*)&Qs[row * 68 + c4] = o;
    }
    // ---- load K (tf32), rows >= 196 zeroed
    for (int i = tid; i < 208 * 16; i += 224) {
        int row = i >> 4, c4 = (i & 15) * 4;
        float4 v = make_float4(0.f, 0.f, 0.f, 0.f);
        if (row < SEQ) v = *(const float4*)(Kg + (size_t)row * QKV3 + c4);
        uint4 o;
        o.x = f2tf32(v.x); o.y = f2tf32(v.y);
        o.z = f2tf32(v.z); o.w = f2tf32(v.w);
        *(uint4*)&Ks[row * 68 + c4] = o;
    }
    __syncthreads();

    // ---- scores: warp strip 16 rows x 208 cols, K-dim 64 (8 k-steps)
    float acc[13][2][4];
#pragma unroll
    for (int mg = 0; mg < 13; mg++)
#pragma unroll
        for (int mt = 0; mt < 2; mt++)
#pragma unroll
            for (int t = 0; t < 4; t++) acc[mg][mt][t] = 0.f;

    const int rb = warp * 16;
#pragma unroll
    for (int ks = 0; ks < 8; ks++) {
        int kb = ks * 8;
        unsigned af[4];
        af[0] = Qs[(rb + r)     * 68 + kb + tq];
        af[1] = Qs[(rb + r + 8) * 68 + kb + tq];
        af[2] = Qs[(rb + r)     * 68 + kb + tq + 4];
        af[3] = Qs[(rb + r + 8) * 68 + kb + tq + 4];
#pragma unroll
        for (int mg = 0; mg < 13; mg++)
#pragma unroll
            for (int mt = 0; mt < 2; mt++) {
                int cb = mg * 16 + mt * 8;
                unsigned bf[2];
                bf[0] = Ks[(cb + r) * 68 + kb + tq];
                bf[1] = Ks[(cb + r) * 68 + kb + tq + 4];
                mma_tf32(acc[mg][mt], af, bf);
            }
    }

    // ---- register softmax (4 lanes sharing r hold one row)
    float mx0 = -INFINITY, mx1 = -INFINITY;
#pragma unroll
    for (int mg = 0; mg < 13; mg++)
#pragma unroll
        for (int mt = 0; mt < 2; mt++)
#pragma unroll
            for (int j = 0; j < 2; j++) {
                bool valid = (mg < 12) || (mt == 0 && (2 * tq + j) < 4);
                if (valid) {
                    mx0 = fmaxf(mx0, acc[mg][mt][j]);
                    mx1 = fmaxf(mx1, acc[mg][mt][2 + j]);
                }
            }
    mx0 = fmaxf(mx0, __shfl_xor_sync(0xffffffffu, mx0, 1));
    mx0 = fmaxf(mx0, __shfl_xor_sync(0xffffffffu, mx0, 2));
    mx1 = fmaxf(mx1, __shfl_xor_sync(0xffffffffu, mx1, 1));
    mx1 = fmaxf(mx1, __shfl_xor_sync(0xffffffffu, mx1, 2));

    float sum0 = 0.f, sum1 = 0.f;
#pragma unroll
    for (int mg = 0; mg < 13; mg++)
#pragma unroll
        for (int mt = 0; mt < 2; mt++)
#pragma unroll
            for (int j = 0; j < 2; j++) {
                bool valid = (mg < 12) || (mt == 0 && (2 * tq + j) < 4);
                float e0 = valid ? __expf(acc[mg][mt][j]     - mx0) : 0.f;
                float e1 = valid ? __expf(acc[mg][mt][2 + j] - mx1) : 0.f;
                acc[mg][mt][j]     = e0;
                acc[mg][mt][2 + j] = e1;
                sum0 += e0;
                sum1 += e1;
            }
    sum0 += __shfl_xor_sync(0xffffffffu, sum0, 1);
    sum0 += __shfl_xor_sync(0xffffffffu, sum0, 2);
    sum1 += __shfl_xor_sync(0xffffffffu, sum1, 1);
    sum1 += __shfl_xor_sync(0xffffffffu, sum1, 2);
    const float inv0 = 1.f / sum0;
    const float inv1 = 1.f / sum1;

    // ---- normalize + static_a bias, in registers (P = softmax + A)
    const int row0 = rb + r, row1 = rb + r + 8;
    const float* ar0 = sa + ((size_t)h * SEQ + q0 + row0) * SEQ;
    const float* ar1 = sa + ((size_t)h * SEQ + q0 + row1) * SEQ;
    const bool rOk0 = row0 < 98, rOk1 = row1 < 98;
#pragma unroll
    for (int mg = 0; mg < 13; mg++)
#pragma unroll
        for (int mt = 0; mt < 2; mt++) {
            int c = mg * 16 + mt * 8 + 2 * tq;
#pragma unroll
            for (int j = 0; j < 2; j++) {
                bool valid = (mg < 12) || (mt == 0 && (2 * tq + j) < 4);
                float a0 = (valid && rOk0) ? ar0[c + j] : 0.f;
                float a1 = (valid && rOk1) ? ar1[c + j] : 0.f;
                acc[mg][mt][j]     = valid ? acc[mg][mt][j]     * inv0 + a0 : 0.f;
                acc[mg][mt][2 + j] = valid ? acc[mg][mt][2 + j] * inv1 + a1 : 0.f;
            }
        }

    // ---- swap K -> V in the shared union buffer
    __syncthreads();   // all warps done reading Ks
    for (int i = tid; i < 208 * 16; i += 224) {
        int row = i >> 4, c4 = (i & 15) * 4;
        float4 v = make_float4(0.f, 0.f, 0.f, 0.f);
        if (row < SEQ) v = *(const float4*)(Vg + (size_t)row * QKV3 + c4);
        uint4 o;
        o.x = f2tf32(v.x); o.y = f2tf32(v.y);
        o.z = f2tf32(v.z); o.w = f2tf32(v.w);
        *(uint4*)&Vs[row * 72 + c4] = o;
    }
    __syncthreads();

    // ---- AV: P (C-frag) -> A-frag via quad shuffles, mma against V
    float out[8][4];
#pragma unroll
    for (int nt = 0; nt < 8; nt++)
#pragma unroll
        for (int t = 0; t < 4; t++) out[nt][t] = 0.f;

    const int srcA = (lane & ~3) | (tq >> 1);
    const int srcB = srcA + 2;
    const bool jsel = (tq & 1);

#pragma unroll
    for (int mg = 0; mg < 13; mg++) {
#pragma unroll
        for (int mt = 0; mt < 2; mt++) {
            float p0a = __shfl_sync(0xffffffffu, acc[mg][mt][0], srcA);
            float p1a = __shfl_sync(0xffffffffu, acc[mg][mt][1], srcA);
            float p0b = __shfl_sync(0xffffffffu, acc[mg][mt][0], srcB);
            float p1b = __shfl_sync(0xffffffffu, acc[mg][mt][1], srcB);
            float p2a = __shfl_sync(0xffffffffu, acc[mg][mt][2], srcA);
            float p3a = __shfl_sync(0xffffffffu, acc[mg][mt][3], srcA);
            float p2b = __shfl_sync(0xffffffffu, acc[mg][mt][2], srcB);
            float p3b = __shfl_sync(0xffffffffu, acc[mg][mt][3], srcB);
            unsigned af[4];
            af[0] = f2tf32(jsel ? p1a : p0a);
            af[1] = f2tf32(jsel ? p3a : p2a);
            af[2] = f2tf32(jsel ? p1b : p0b);
            af[3] = f2tf32(jsel ? p3b : p2b);
            const int kb = mg * 16 + mt * 8;
#pragma unroll
            for (int nt = 0; nt < 8; nt++) {
                unsigned bf[2];
                bf[0] = Vs[(kb + tq)     * 72 + nt * 8 + r];
                bf[1] = Vs[(kb + tq + 4) * 72 + nt * 8 + r];
                mma_tf32(out[nt], af, bf);
            }
        }
    }

    // ---- store out strip
    float* og = ao + (size_t)b * SEQ * DIMC + h * HD;
#pragma unroll
    for (int nt = 0; nt < 8; nt++) {
        int c = nt * 8 + 2 * tq;
        if (rOk0)
            *(float2*)(og + (size_t)(q0 + row0) * DIMC + c) =
                make_float2(out[nt][0], out[nt][1]);
        if (rOk1)
            *(float2*)(og + (size_t)(q0 + row1) * DIMC + c) =
                make_float2(out[nt][2], out[nt][3]);
    }
}

// ---------------- launch ----------------------------------------------------
extern "C" void kernel_launch(void* const* d_in, const int* in_sizes, int n_in,
                              void* d_out, int out_size)
{
    const float* x     = (const float*)d_in[0];  // [64,196,768]
    const float* Wqkv  = (const float*)d_in[1];  // [768,2304]
    const float* sa    = (const float*)d_in[2];  // [1,12,196,196]
    const float* Wproj = (const float*)d_in[3];  // [768,768]
    const float* bproj = (const float*)d_in[4];  // [768]
    float* out = (float*)d_out;                  // [64,196,768]

    void *p_qkv, *p_ao;
    cudaGetSymbolAddress(&p_qkv, g_qkv);
    cudaGetSymbolAddress(&p_ao, g_ao);
    float* qkv = (float*)p_qkv;
    float* ao  = (float*)p_ao;

    static int smem_set = 0;
    if (!smem_set) {
        cudaFuncSetAttribute(attn_fused_kernel,
                             cudaFuncAttributeMaxDynamicSharedMemorySize,
                             FA_SMEM_BYTES);
        smem_set = 1;
    }

    // 1) QKV GEMM (warp tile 64x64, 128 threads)
    gemm_tf32_kernel<<<dim3(QKV3 / TBN, BN / TBM), 128>>>(x, Wqkv, nullptr, qkv,
                                                          BN, QKV3, DIMC, 0);
    // 2) fused scores + register softmax + bias + AV
    attn_fused_kernel<<<NBLK, 224, FA_SMEM_BYTES>>>(qkv, sa, ao);
    // 3) output projection + bias
    gemm_tf32_kernel<<<dim3(DIMC / TBN, BN / TBM), 128>>>(ao, Wproj, bproj, out,
                                                          BN, DIMC, DIMC, 1);
}